// round 4
// baseline (speedup 1.0000x reference)
#include <cuda_runtime.h>
#include <cuda_bf16.h>

// LIF neuron forward over T=16 timesteps.
// x: [B=16, C=64, T=16, H=64, W=64] fp32, decay: [1] fp32.
// out[b,c,t,h,w] = spike_t where:
//   mem_t = mem_{t-1} * sigmoid(decay) * (1 - spike_{t-1}) + x_t
//   spike_t = (mem_t > 0.5) ? 1 : 0
//
// Pure HBM-streaming kernel (512 MB traffic, zero reuse).
// R1-R3 lessons: plain LDG/STG beats .cs hints; occupancy >> per-thread MLP;
// ptxas's natural scheduling at regs~30 is optimal. This round: persistent
// grid-stride launch (grid = 8 CTA/SM * 148 SM = 1184) to eliminate the
// 3.46-wave quantization + wave-transition overhead of the 4096-block grid.

#define T_STEPS 16
#define HW 4096                    // 64*64
#define BC 1024                    // 16*64
#define VEC4_PER_PLANE (HW / 4)    // 1024 float4 per (bc,t) plane
#define NUM_CHUNKS 4096            // BC * VEC4_PER_PLANE / 256
#define PERSISTENT_BLOCKS 1184     // 8 CTAs/SM * 148 SMs

__global__ __launch_bounds__(256) void lif_kernel(
    const float* __restrict__ x,
    const float* __restrict__ decay,
    float* __restrict__ out)
{
    const float d  = decay[0];
    const float ds = 1.0f / (1.0f + __expf(-d));

    for (unsigned chunk = blockIdx.x; chunk < NUM_CHUNKS; chunk += gridDim.x) {
        const unsigned g  = chunk * 256u + threadIdx.x;
        const unsigned bc = g >> 10;        // which (b,c) slab
        const unsigned s4 = g & 1023u;      // which float4 within the HW plane

        const size_t base = (size_t)bc * (T_STEPS * HW) + (size_t)s4 * 4;

        const float4* __restrict__ xin  = (const float4*)(x + base);
        float4* __restrict__ xout = (float4*)(out + base);

        float4 mem = make_float4(0.f, 0.f, 0.f, 0.f);
        float4 spk = make_float4(0.f, 0.f, 0.f, 0.f);

#pragma unroll
        for (int t = 0; t < T_STEPS; t++) {
            float4 xv = xin[(size_t)t * VEC4_PER_PLANE];

            mem.x = mem.x * ds * (1.0f - spk.x) + xv.x;
            mem.y = mem.y * ds * (1.0f - spk.y) + xv.y;
            mem.z = mem.z * ds * (1.0f - spk.z) + xv.z;
            mem.w = mem.w * ds * (1.0f - spk.w) + xv.w;

            spk.x = (mem.x > 0.5f) ? 1.0f : 0.0f;
            spk.y = (mem.y > 0.5f) ? 1.0f : 0.0f;
            spk.z = (mem.z > 0.5f) ? 1.0f : 0.0f;
            spk.w = (mem.w > 0.5f) ? 1.0f : 0.0f;

            xout[(size_t)t * VEC4_PER_PLANE] = spk;
        }
    }
}

extern "C" void kernel_launch(void* const* d_in, const int* in_sizes, int n_in,
                              void* d_out, int out_size)
{
    const float* x     = (const float*)d_in[0];
    const float* decay = (const float*)d_in[1];
    float* out = (float*)d_out;

    lif_kernel<<<PERSISTENT_BLOCKS, 256>>>(x, decay, out);
}

// round 5
// speedup vs baseline: 1.0320x; 1.0320x over previous
#include <cuda_runtime.h>
#include <cuda_bf16.h>

// LIF neuron forward over T=16 timesteps.
// x: [B=16, C=64, T=16, H=64, W=64] fp32, decay: [1] fp32.
// out[b,c,t,h,w] = spike_t where:
//   mem_t = mem_{t-1} * sigmoid(decay) * (1 - spike_{t-1}) + x_t
//   spike_t = (mem_t > 0.5) ? 1 : 0
//
// Pure HBM-streaming kernel (512 MB traffic, zero reuse); measured to be
// pinned at the ~6.4 TB/s mixed read/write DRAM ceiling in all configs.
// R1-R4 lessons: no .cs hints, no grid-stride persistence, occupancy >= ~70%
// is sufficient. This round: batch-4 load/store grouping (plain LDG/STG) to
// create same-direction DRAM bursts (4 reads, then 4 writes) while keeping
// regs ~44 (6 CTAs/SM).

#define T_STEPS 16
#define HW 4096                    // 64*64
#define BC 1024                    // 16*64
#define VEC4_PER_PLANE (HW / 4)    // 1024 float4 per (bc,t) plane
#define BATCH 4

__global__ __launch_bounds__(256) void lif_kernel(
    const float* __restrict__ x,
    const float* __restrict__ decay,
    float* __restrict__ out)
{
    const float d  = decay[0];
    const float ds = 1.0f / (1.0f + __expf(-d));

    const unsigned g  = blockIdx.x * blockDim.x + threadIdx.x;
    const unsigned bc = g >> 10;        // which (b,c) slab
    const unsigned s4 = g & 1023u;      // which float4 within the HW plane

    const size_t base = (size_t)bc * (T_STEPS * HW) + (size_t)s4 * 4;

    const float4* __restrict__ xin  = (const float4*)(x + base);
    float4* __restrict__ xout = (float4*)(out + base);

    float4 mem = make_float4(0.f, 0.f, 0.f, 0.f);
    float4 spk = make_float4(0.f, 0.f, 0.f, 0.f);

#pragma unroll
    for (int tb = 0; tb < T_STEPS; tb += BATCH) {
        // read burst: BATCH independent 128-bit loads
        float4 xv[BATCH];
#pragma unroll
        for (int j = 0; j < BATCH; j++)
            xv[j] = xin[(size_t)(tb + j) * VEC4_PER_PLANE];

        // recurrence for this batch
        float4 sp[BATCH];
#pragma unroll
        for (int j = 0; j < BATCH; j++) {
            mem.x = mem.x * ds * (1.0f - spk.x) + xv[j].x;
            mem.y = mem.y * ds * (1.0f - spk.y) + xv[j].y;
            mem.z = mem.z * ds * (1.0f - spk.z) + xv[j].z;
            mem.w = mem.w * ds * (1.0f - spk.w) + xv[j].w;

            spk.x = (mem.x > 0.5f) ? 1.0f : 0.0f;
            spk.y = (mem.y > 0.5f) ? 1.0f : 0.0f;
            spk.z = (mem.z > 0.5f) ? 1.0f : 0.0f;
            spk.w = (mem.w > 0.5f) ? 1.0f : 0.0f;

            sp[j] = spk;
        }

        // write burst: BATCH 128-bit stores
#pragma unroll
        for (int j = 0; j < BATCH; j++)
            xout[(size_t)(tb + j) * VEC4_PER_PLANE] = sp[j];
    }
}

extern "C" void kernel_launch(void* const* d_in, const int* in_sizes, int n_in,
                              void* d_out, int out_size)
{
    const float* x     = (const float*)d_in[0];
    const float* decay = (const float*)d_in[1];
    float* out = (float*)d_out;

    const int threads = 256;
    const int blocks  = (BC * VEC4_PER_PLANE) / threads;  // 4096
    lif_kernel<<<blocks, threads>>>(x, decay, out);
}

// round 6
// speedup vs baseline: 1.0327x; 1.0008x over previous
#include <cuda_runtime.h>
#include <cuda_bf16.h>

// LIF neuron forward over T=16 timesteps.
// x: [B=16, C=64, T=16, H=64, W=64] fp32, decay: [1] fp32.
// out[b,c,t,h,w] = spike_t where:
//   mem_t = mem_{t-1} * sigmoid(decay) * (1 - spike_{t-1}) + x_t
//   spike_t = (mem_t > 0.5) ? 1 : 0
//
// Pure HBM-streaming kernel (512 MB traffic, zero reuse), pinned at the
// ~6.3 TB/s mixed read/write DRAM ceiling. Session finding: the best
// *harness* (graph-replay, NAT-clock) time came from the config with
// maximal same-direction burst separation (batch-16 + .cs), despite its
// low occupancy. This round: batch-8 + .cs — same burst-separation
// mechanism at half the register cost (occ ~60%).

#define T_STEPS 16
#define HW 4096                    // 64*64
#define BC 1024                    // 16*64
#define VEC4_PER_PLANE (HW / 4)    // 1024 float4 per (bc,t) plane
#define BATCH 8

__global__ __launch_bounds__(256) void lif_kernel(
    const float* __restrict__ x,
    const float* __restrict__ decay,
    float* __restrict__ out)
{
    const float d  = decay[0];
    const float ds = 1.0f / (1.0f + __expf(-d));

    const unsigned g  = blockIdx.x * blockDim.x + threadIdx.x;
    const unsigned bc = g >> 10;        // which (b,c) slab
    const unsigned s4 = g & 1023u;      // which float4 within the HW plane

    const size_t base = (size_t)bc * (T_STEPS * HW) + (size_t)s4 * 4;

    const float4* __restrict__ xin  = (const float4*)(x + base);
    float4* __restrict__ xout = (float4*)(out + base);

    float4 mem = make_float4(0.f, 0.f, 0.f, 0.f);
    float4 spk = make_float4(0.f, 0.f, 0.f, 0.f);

#pragma unroll
    for (int tb = 0; tb < T_STEPS; tb += BATCH) {
        // read burst: BATCH independent 128-bit streaming loads
        float4 xv[BATCH];
#pragma unroll
        for (int j = 0; j < BATCH; j++)
            xv[j] = __ldcs(&xin[(size_t)(tb + j) * VEC4_PER_PLANE]);

        // recurrence for this batch (sequential FMA chain, cheap)
        float4 sp[BATCH];
#pragma unroll
        for (int j = 0; j < BATCH; j++) {
            mem.x = mem.x * ds * (1.0f - spk.x) + xv[j].x;
            mem.y = mem.y * ds * (1.0f - spk.y) + xv[j].y;
            mem.z = mem.z * ds * (1.0f - spk.z) + xv[j].z;
            mem.w = mem.w * ds * (1.0f - spk.w) + xv[j].w;

            spk.x = (mem.x > 0.5f) ? 1.0f : 0.0f;
            spk.y = (mem.y > 0.5f) ? 1.0f : 0.0f;
            spk.z = (mem.z > 0.5f) ? 1.0f : 0.0f;
            spk.w = (mem.w > 0.5f) ? 1.0f : 0.0f;

            sp[j] = spk;
        }

        // write burst: BATCH 128-bit streaming stores
#pragma unroll
        for (int j = 0; j < BATCH; j++)
            __stcs(&xout[(size_t)(tb + j) * VEC4_PER_PLANE], sp[j]);
    }
}

extern "C" void kernel_launch(void* const* d_in, const int* in_sizes, int n_in,
                              void* d_out, int out_size)
{
    const float* x     = (const float*)d_in[0];
    const float* decay = (const float*)d_in[1];
    float* out = (float*)d_out;

    const int threads = 256;
    const int blocks  = (BC * VEC4_PER_PLANE) / threads;  // 4096
    lif_kernel<<<blocks, threads>>>(x, decay, out);
}

// round 7
// speedup vs baseline: 1.0495x; 1.0163x over previous
#include <cuda_runtime.h>
#include <cuda_bf16.h>

// LIF neuron forward over T=16 timesteps.
// x: [B=16, C=64, T=16, H=64, W=64] fp32, decay: [1] fp32.
// out[b,c,t,h,w] = spike_t where:
//   mem_t = mem_{t-1} * sigmoid(decay) * (1 - spike_{t-1}) + x_t
//   spike_t = (mem_t > 0.5) ? 1 : 0
//
// Pure HBM-streaming kernel (512 MB traffic, zero reuse), measured at
// ~6.26 TB/s ~= 90% of the B300 LTS chip cap; structure-invariant plateau.
// This is the R2 config (batch-16 + .cs streaming hints), resubmitted
// verbatim as a reproduction bench: it posted the session-best 82.6 us
// harness time and rigor requires confirming before final selection.
// Mechanism if real: full read-burst/write-burst stream separation per
// thread (16 LDG.128 then 16 STG.128) + evict-first L2 policy, with low
// occupancy (31%) reducing cross-CTA L1tex wavefront-queue contention.

#define T_STEPS 16
#define HW 4096                    // 64*64
#define BC 1024                    // 16*64
#define VEC4_PER_PLANE (HW / 4)    // 1024 float4 per (bc,t) plane

__global__ __launch_bounds__(256) void lif_kernel(
    const float* __restrict__ x,
    const float* __restrict__ decay,
    float* __restrict__ out)
{
    const float d  = decay[0];
    const float ds = 1.0f / (1.0f + __expf(-d));

    const unsigned g  = blockIdx.x * blockDim.x + threadIdx.x;
    const unsigned bc = g >> 10;        // which (b,c) slab
    const unsigned s4 = g & 1023u;      // which float4 within the HW plane

    const size_t base = (size_t)bc * (T_STEPS * HW) + (size_t)s4 * 4;

    const float4* __restrict__ xin  = (const float4*)(x + base);
    float4* __restrict__ xout = (float4*)(out + base);

    // ---- phase 1: batch all 16 independent loads (MLP=16) ----
    float4 xv[T_STEPS];
#pragma unroll
    for (int t = 0; t < T_STEPS; t++) {
        xv[t] = __ldcs(&xin[(size_t)t * VEC4_PER_PLANE]);
    }

    // ---- phase 2: sequential recurrence + burst stores ----
    float4 mem = make_float4(0.f, 0.f, 0.f, 0.f);
    float4 spk = make_float4(0.f, 0.f, 0.f, 0.f);

#pragma unroll
    for (int t = 0; t < T_STEPS; t++) {
        mem.x = mem.x * ds * (1.0f - spk.x) + xv[t].x;
        mem.y = mem.y * ds * (1.0f - spk.y) + xv[t].y;
        mem.z = mem.z * ds * (1.0f - spk.z) + xv[t].z;
        mem.w = mem.w * ds * (1.0f - spk.w) + xv[t].w;

        spk.x = (mem.x > 0.5f) ? 1.0f : 0.0f;
        spk.y = (mem.y > 0.5f) ? 1.0f : 0.0f;
        spk.z = (mem.z > 0.5f) ? 1.0f : 0.0f;
        spk.w = (mem.w > 0.5f) ? 1.0f : 0.0f;

        __stcs(&xout[(size_t)t * VEC4_PER_PLANE], spk);
    }
}

extern "C" void kernel_launch(void* const* d_in, const int* in_sizes, int n_in,
                              void* d_out, int out_size)
{
    const float* x     = (const float*)d_in[0];
    const float* decay = (const float*)d_in[1];
    float* out = (float*)d_out;

    const int threads = 256;
    const int blocks  = (BC * VEC4_PER_PLANE) / threads;  // 4096
    lif_kernel<<<blocks, threads>>>(x, decay, out);
}